// round 1
// baseline (speedup 1.0000x reference)
#include <cuda_runtime.h>
#include <cstdint>
#include <cstddef>

// Problem dims (fixed by the dataset)
#define M_DIM 8192
#define N_DIM 4096
#define K_DIM 4096

#define BM 128
#define BN 128
#define BK 32
#define STAGES 3
#define SMEM_FLOATS_PER_STAGE (2 * BM * BK)   // A tile + B tile = 8192 floats
#define SMEM_BYTES (STAGES * SMEM_FLOATS_PER_STAGE * 4)

// Scratch (allocation-free rule: __device__ globals)
__device__ float g_Wp[(size_t)N_DIM * K_DIM];     // W + 2*B@A, tf32-rounded  (64 MB)
__device__ float g_Xp[(size_t)M_DIM * K_DIM];     // x, tf32-rounded          (128 MB)
__device__ float g_biasp[N_DIM];                  // bias + 2*delta_bias

// ---------------------------------------------------------------------------
// helpers
// ---------------------------------------------------------------------------
__device__ __forceinline__ float tf32_rn(float x) {
    uint32_t u;
    asm volatile("cvt.rna.tf32.f32 %0, %1;\n" : "=r"(u) : "f"(x));
    return __uint_as_float(u);
}

__device__ __forceinline__ void cp16(float* smem_ptr, const float* gmem_ptr) {
    uint32_t sa = (uint32_t)__cvta_generic_to_shared(smem_ptr);
    asm volatile("cp.async.cg.shared.global [%0], [%1], 16;\n"
                 :: "r"(sa), "l"(gmem_ptr));
}

__device__ __forceinline__ void ldsm4(uint32_t& r0, uint32_t& r1, uint32_t& r2, uint32_t& r3,
                                      const float* p) {
    uint32_t sa = (uint32_t)__cvta_generic_to_shared(p);
    asm volatile("ldmatrix.sync.aligned.m8n8.x4.shared.b16 {%0,%1,%2,%3}, [%4];\n"
                 : "=r"(r0), "=r"(r1), "=r"(r2), "=r"(r3) : "r"(sa));
}

__device__ __forceinline__ void mma_tf32(float* d, const uint32_t* a, uint32_t b0, uint32_t b1) {
    asm volatile(
        "mma.sync.aligned.m16n8k8.row.col.f32.tf32.tf32.f32 "
        "{%0,%1,%2,%3},{%4,%5,%6,%7},{%8,%9},{%0,%1,%2,%3};\n"
        : "+f"(d[0]), "+f"(d[1]), "+f"(d[2]), "+f"(d[3])
        : "r"(a[0]), "r"(a[1]), "r"(a[2]), "r"(a[3]), "r"(b0), "r"(b1));
}

// ---------------------------------------------------------------------------
// prep kernels
// ---------------------------------------------------------------------------

// W' = tf32_rn(W + 2 * B @ A)     W:[N,K], B:[N,16], A:[16,K]
__global__ void prep_w(const float* __restrict__ W,
                       const float* __restrict__ B,
                       const float* __restrict__ A) {
    __shared__ float As[16][128];
    __shared__ float Bs[16][16];
    const int k0 = blockIdx.x * 128;
    const int n0 = blockIdx.y * 16;
    const int tid = threadIdx.x;

    for (int i = tid; i < 16 * 128; i += 256) {
        int r = i / 128, kk = i % 128;
        As[r][kk] = A[(size_t)r * K_DIM + k0 + kk];
    }
    {
        int nn = tid / 16, r = tid % 16;
        Bs[nn][r] = B[(size_t)(n0 + nn) * 16 + r];
    }
    __syncthreads();

    for (int i = tid; i < 16 * 128; i += 256) {
        int nn = i / 128, kk = i % 128;
        float acc = 0.f;
        #pragma unroll
        for (int r = 0; r < 16; ++r) acc += Bs[nn][r] * As[r][kk];
        size_t idx = (size_t)(n0 + nn) * K_DIM + k0 + kk;
        g_Wp[idx] = tf32_rn(W[idx] + 2.0f * acc);
    }
}

// Xp = tf32_rn(x)
__global__ void prep_x(const float* __restrict__ x) {
    size_t i = (size_t)blockIdx.x * 256 + threadIdx.x;   // float4 index
    float4 v = ((const float4*)x)[i];
    v.x = tf32_rn(v.x); v.y = tf32_rn(v.y);
    v.z = tf32_rn(v.z); v.w = tf32_rn(v.w);
    ((float4*)g_Xp)[i] = v;
}

// bias' = bias + 2*delta_bias
__global__ void prep_bias(const float* __restrict__ bias, const float* __restrict__ db) {
    int i = blockIdx.x * 256 + threadIdx.x;
    if (i < N_DIM) g_biasp[i] = bias[i] + 2.0f * db[i];
}

// ---------------------------------------------------------------------------
// main GEMM: out[M,N] = Xp[M,K] @ Wp[N,K]^T + bias'
// ---------------------------------------------------------------------------
__device__ __forceinline__ void issue_stage(float* smem, int st, int kt,
                                            int bM, int bN, int tid) {
    float* sA = smem + st * SMEM_FLOATS_PER_STAGE;
    float* sB = sA + BM * BK;
    const float* gA = g_Xp + (size_t)(bM * BM) * K_DIM + (size_t)kt * BK;
    const float* gB = g_Wp + (size_t)(bN * BN) * K_DIM + (size_t)kt * BK;
    #pragma unroll
    for (int i = 0; i < 4; ++i) {
        int u = tid + i * 256;          // 1024 16B-granules per tile
        int m = u >> 3;                 // row 0..127
        int g = u & 7;                  // granule 0..7 (4 floats each)
        int slot = g ^ (m & 7);         // XOR swizzle at 16B granularity
        cp16(sA + m * BK + (slot << 2), gA + (size_t)m * K_DIM + g * 4);
        cp16(sB + m * BK + (slot << 2), gB + (size_t)m * K_DIM + g * 4);
    }
}

__global__ __launch_bounds__(256, 1) void gemm_tf32(float* __restrict__ out) {
    extern __shared__ float smem[];
    const int tid   = threadIdx.x;
    const int lane  = tid & 31;
    const int warp  = tid >> 5;
    const int warpM = warp & 3;   // 4 warps over M (4*32 = 128)
    const int warpN = warp >> 2;  // 2 warps over N (2*64 = 128)
    const int bN = blockIdx.x;
    const int bM = blockIdx.y;

    float acc[2][8][4];
    #pragma unroll
    for (int i = 0; i < 2; ++i)
        #pragma unroll
        for (int j = 0; j < 8; ++j)
            #pragma unroll
            for (int k = 0; k < 4; ++k) acc[i][j][k] = 0.f;

    const int KT = K_DIM / BK;   // 128

    // prologue
    #pragma unroll
    for (int s = 0; s < STAGES - 1; ++s) {
        issue_stage(smem, s, s, bM, bN, tid);
        asm volatile("cp.async.commit_group;\n" ::: "memory");
    }

    for (int kt = 0; kt < KT; ++kt) {
        int fetch = kt + STAGES - 1;
        if (fetch < KT) issue_stage(smem, fetch % STAGES, fetch, bM, bN, tid);
        asm volatile("cp.async.commit_group;\n" ::: "memory");
        asm volatile("cp.async.wait_group 2;\n" ::: "memory");
        __syncthreads();

        const float* sA = smem + (kt % STAGES) * SMEM_FLOATS_PER_STAGE;
        const float* sB = sA + BM * BK;

        #pragma unroll
        for (int s = 0; s < 4; ++s) {   // 4 k-steps of 8 per BK=32
            uint32_t af[2][4];
            #pragma unroll
            for (int mi = 0; mi < 2; ++mi) {
                int m = warpM * 32 + mi * 16 + (lane & 15);
                int g = 2 * s + (lane >> 4);
                int slot = g ^ (m & 7);
                ldsm4(af[mi][0], af[mi][1], af[mi][2], af[mi][3],
                      sA + m * BK + (slot << 2));
            }
            uint32_t bf[4][4];
            #pragma unroll
            for (int p = 0; p < 4; ++p) {
                int n = warpN * 64 + p * 16 + (lane & 7) + ((lane >> 4) << 3);
                int g = 2 * s + ((lane >> 3) & 1);
                int slot = g ^ (n & 7);
                ldsm4(bf[p][0], bf[p][1], bf[p][2], bf[p][3],
                      sB + n * BK + (slot << 2));
            }
            #pragma unroll
            for (int mi = 0; mi < 2; ++mi)
                #pragma unroll
                for (int p = 0; p < 4; ++p) {
                    mma_tf32(acc[mi][2 * p],     af[mi], bf[p][0], bf[p][1]);
                    mma_tf32(acc[mi][2 * p + 1], af[mi], bf[p][2], bf[p][3]);
                }
        }
        __syncthreads();
    }

    // epilogue: add bias', store float2
    const int row0 = bM * BM + warpM * 32 + (lane >> 2);
    const int col0 = bN * BN + warpN * 64 + (lane & 3) * 2;
    #pragma unroll
    for (int mi = 0; mi < 2; ++mi) {
        #pragma unroll
        for (int ni = 0; ni < 8; ++ni) {
            int c = col0 + ni * 8;
            float b0 = g_biasp[c], b1 = g_biasp[c + 1];
            #pragma unroll
            for (int h = 0; h < 2; ++h) {
                int r = row0 + mi * 16 + h * 8;
                float2 v;
                v.x = acc[mi][ni][2 * h]     + b0;
                v.y = acc[mi][ni][2 * h + 1] + b1;
                *reinterpret_cast<float2*>(out + (size_t)r * N_DIM + c) = v;
            }
        }
    }
}

// ---------------------------------------------------------------------------
extern "C" void kernel_launch(void* const* d_in, const int* in_sizes, int n_in,
                              void* d_out, int out_size) {
    const float* x          = (const float*)d_in[0];
    const float* W          = (const float*)d_in[1];
    const float* bias       = (const float*)d_in[2];
    const float* B_lora     = (const float*)d_in[3];
    const float* A_lora     = (const float*)d_in[4];
    const float* delta_bias = (const float*)d_in[5];
    float* out = (float*)d_out;

    cudaFuncSetAttribute(gemm_tf32, cudaFuncAttributeMaxDynamicSharedMemorySize, SMEM_BYTES);

    prep_x<<<(M_DIM * (size_t)K_DIM) / 4 / 256, 256>>>(x);
    prep_w<<<dim3(K_DIM / 128, N_DIM / 16), 256>>>(W, B_lora, A_lora);
    prep_bias<<<(N_DIM + 255) / 256, 256>>>(bias, delta_bias);
    gemm_tf32<<<dim3(N_DIM / BN, M_DIM / BM), 256, SMEM_BYTES>>>(out);
}

// round 3
// speedup vs baseline: 1.3529x; 1.3529x over previous
#include <cuda_runtime.h>
#include <cstdint>
#include <cstddef>

// Problem dims (fixed by the dataset)
#define M_DIM 8192
#define N_DIM 4096
#define K_DIM 4096

#define BM 128
#define BN 128
#define BK 32
#define STAGES 3
#define A_BYTES (BM * BK * 4)                 // 16384
#define STAGE_BYTES (2 * A_BYTES)             // 32768 (A tile + B tile)
#define SMEM_BYTES (STAGES * STAGE_BYTES)     // 98304

// Scratch (allocation-free rule: __device__ globals)
__device__ float g_Wp[(size_t)N_DIM * K_DIM];     // W + 2*B@A, tf32-rounded  (64 MB)
__device__ float g_Xp[(size_t)M_DIM * K_DIM];     // x, tf32-rounded          (128 MB)
__device__ float g_biasp[N_DIM];                  // bias + 2*delta_bias

// ---------------------------------------------------------------------------
// helpers
// ---------------------------------------------------------------------------
__device__ __forceinline__ float tf32_rn(float x) {
    uint32_t u;
    asm volatile("cvt.rna.tf32.f32 %0, %1;\n" : "=r"(u) : "f"(x));
    return __uint_as_float(u);
}

__device__ __forceinline__ void cp16(uint32_t smem_dst, const void* gmem_ptr) {
    asm volatile("cp.async.cg.shared.global [%0], [%1], 16;\n"
                 :: "r"(smem_dst), "l"(gmem_ptr));
}

__device__ __forceinline__ void ldsm4(uint32_t& r0, uint32_t& r1, uint32_t& r2, uint32_t& r3,
                                      uint32_t saddr) {
    asm volatile("ldmatrix.sync.aligned.m8n8.x4.shared.b16 {%0,%1,%2,%3}, [%4];\n"
                 : "=r"(r0), "=r"(r1), "=r"(r2), "=r"(r3) : "r"(saddr));
}

__device__ __forceinline__ void mma_tf32(float* d, const uint32_t* a, uint32_t b0, uint32_t b1) {
    asm volatile(
        "mma.sync.aligned.m16n8k8.row.col.f32.tf32.tf32.f32 "
        "{%0,%1,%2,%3},{%4,%5,%6,%7},{%8,%9},{%0,%1,%2,%3};\n"
        : "+f"(d[0]), "+f"(d[1]), "+f"(d[2]), "+f"(d[3])
        : "r"(a[0]), "r"(a[1]), "r"(a[2]), "r"(a[3]), "r"(b0), "r"(b1));
}

// ---------------------------------------------------------------------------
// prep kernels
// ---------------------------------------------------------------------------

// W' = tf32_rn(W + 2 * B @ A)     W:[N,K], B:[N,16], A:[16,K]
__global__ void prep_w(const float* __restrict__ W,
                       const float* __restrict__ B,
                       const float* __restrict__ A) {
    __shared__ float As[16][128];
    __shared__ float Bs[16][16];
    const int k0 = blockIdx.x * 128;
    const int n0 = blockIdx.y * 16;
    const int tid = threadIdx.x;

    for (int i = tid; i < 16 * 128; i += 256) {
        int r = i >> 7, kk = i & 127;
        As[r][kk] = A[(size_t)r * K_DIM + k0 + kk];
    }
    {
        int nn = tid >> 4, r = tid & 15;
        Bs[nn][r] = B[(size_t)(n0 + nn) * 16 + r];
    }
    __syncthreads();

    #pragma unroll
    for (int it = 0; it < 2; ++it) {
        int u = tid + it * 256;
        int nn = u >> 5;          // local n row (0..15)
        int gg = u & 31;          // float4 granule within 128 k's
        int n = n0 + nn;
        int k = k0 + gg * 4;
        float4 w = *reinterpret_cast<const float4*>(W + (size_t)n * K_DIM + k);
        float a0 = 0.f, a1 = 0.f, a2 = 0.f, a3 = 0.f;
        int kl = gg * 4;
        #pragma unroll
        for (int r = 0; r < 16; ++r) {
            float b = Bs[nn][r];
            a0 += b * As[r][kl];
            a1 += b * As[r][kl + 1];
            a2 += b * As[r][kl + 2];
            a3 += b * As[r][kl + 3];
        }
        w.x = tf32_rn(w.x + 2.0f * a0);
        w.y = tf32_rn(w.y + 2.0f * a1);
        w.z = tf32_rn(w.z + 2.0f * a2);
        w.w = tf32_rn(w.w + 2.0f * a3);
        *reinterpret_cast<float4*>(g_Wp + (size_t)n * K_DIM + k) = w;
    }
}

// Xp = tf32_rn(x)
__global__ void prep_x(const float* __restrict__ x) {
    size_t i = (size_t)blockIdx.x * 256 + threadIdx.x;   // float4 index
    float4 v = ((const float4*)x)[i];
    v.x = tf32_rn(v.x); v.y = tf32_rn(v.y);
    v.z = tf32_rn(v.z); v.w = tf32_rn(v.w);
    ((float4*)g_Xp)[i] = v;
}

// bias' = bias + 2*delta_bias
__global__ void prep_bias(const float* __restrict__ bias, const float* __restrict__ db) {
    int i = blockIdx.x * 256 + threadIdx.x;
    if (i < N_DIM) g_biasp[i] = bias[i] + 2.0f * db[i];
}

// ---------------------------------------------------------------------------
// main GEMM: out[M,N] = Xp[M,K] @ Wp[N,K]^T + bias'
// ---------------------------------------------------------------------------
__device__ __forceinline__ void issue_stage(uint32_t sbase, int st, int kt,
                                            int bM, int bN, int tid) {
    uint32_t sA = sbase + st * STAGE_BYTES;
    uint32_t sB = sA + A_BYTES;
    const float* gA = g_Xp + (size_t)(bM * BM) * K_DIM + (size_t)kt * BK;
    const float* gB = g_Wp + (size_t)(bN * BN) * K_DIM + (size_t)kt * BK;
    #pragma unroll
    for (int i = 0; i < 4; ++i) {
        int u = tid + i * 256;          // 1024 16B-granules per tile
        int m = u >> 3;                 // row 0..127
        int g = u & 7;                  // granule 0..7 (4 floats each)
        int slot = g ^ (m & 7);         // XOR swizzle at 16B granularity
        cp16(sA + m * 128 + slot * 16, gA + (size_t)m * K_DIM + g * 4);
        cp16(sB + m * 128 + slot * 16, gB + (size_t)m * K_DIM + g * 4);
    }
}

__global__ __launch_bounds__(256, 2) void gemm_tf32(float* __restrict__ out) {
    extern __shared__ float smem_f[];
    const uint32_t sbase = (uint32_t)__cvta_generic_to_shared(smem_f);
    const int tid   = threadIdx.x;
    const int lane  = tid & 31;
    const int warp  = tid >> 5;
    const int warpM = warp & 3;   // 4 warps over M (4*32 = 128)
    const int warpN = warp >> 2;  // 2 warps over N (2*64 = 128)
    const int bN = blockIdx.x;
    const int bM = blockIdx.y;

    float acc[2][8][4];
    #pragma unroll
    for (int i = 0; i < 2; ++i)
        #pragma unroll
        for (int j = 0; j < 8; ++j)
            #pragma unroll
            for (int k = 0; k < 4; ++k) acc[i][j][k] = 0.f;

    // ldsm base addresses (byte offsets within a stage); per k-step s the
    // swizzled address is simply base ^ (s<<5).
    const uint32_t aoff0 = (uint32_t)(warpM * 32 + (lane & 15)) * 128
                         + ((uint32_t)((lane >> 4) ^ (lane & 7)) << 4);
    const uint32_t boff0 = A_BYTES
                         + (uint32_t)(warpN * 64 + (lane & 7) + ((lane >> 4) << 3)) * 128
                         + ((uint32_t)(((lane >> 3) & 1) ^ (lane & 7)) << 4);

    const int KT = K_DIM / BK;   // 128

    // prologue: stages 0,1
    #pragma unroll
    for (int s = 0; s < STAGES - 1; ++s) {
        issue_stage(sbase, s, s, bM, bN, tid);
        asm volatile("cp.async.commit_group;\n" ::: "memory");
    }

    for (int kt = 0; kt < KT; ++kt) {
        asm volatile("cp.async.wait_group 1;\n" ::: "memory");
        __syncthreads();

        // fetch into slot (kt+2)%3 == (kt-1)%3 — safe: sync above proves all
        // warps finished computing that slot in the previous iteration.
        const int fetch = kt + STAGES - 1;
        if (fetch < KT) issue_stage(sbase, fetch % STAGES, fetch, bM, bN, tid);
        asm volatile("cp.async.commit_group;\n" ::: "memory");

        const uint32_t stg = sbase + (kt % STAGES) * STAGE_BYTES;
        const uint32_t aB = stg + aoff0;
        const uint32_t bB = stg + boff0;

        #pragma unroll
        for (int s = 0; s < 4; ++s) {   // 4 k-steps of 8 per BK=32
            const uint32_t sx = (uint32_t)(s << 5);
            uint32_t af[2][4];
            #pragma unroll
            for (int mi = 0; mi < 2; ++mi)
                ldsm4(af[mi][0], af[mi][1], af[mi][2], af[mi][3],
                      (aB + mi * 2048) ^ sx);
            uint32_t bf[4][4];
            #pragma unroll
            for (int p = 0; p < 4; ++p)
                ldsm4(bf[p][0], bf[p][1], bf[p][2], bf[p][3],
                      (bB + p * 2048) ^ sx);
            #pragma unroll
            for (int mi = 0; mi < 2; ++mi)
                #pragma unroll
                for (int p = 0; p < 4; ++p) {
                    mma_tf32(acc[mi][2 * p],     af[mi], bf[p][0], bf[p][1]);
                    mma_tf32(acc[mi][2 * p + 1], af[mi], bf[p][2], bf[p][3]);
                }
        }
    }

    // epilogue: add bias', store float2
    const int row0 = bM * BM + warpM * 32 + (lane >> 2);
    const int col0 = bN * BN + warpN * 64 + (lane & 3) * 2;
    #pragma unroll
    for (int mi = 0; mi < 2; ++mi) {
        #pragma unroll
        for (int ni = 0; ni < 8; ++ni) {
            int c = col0 + ni * 8;
            float b0 = g_biasp[c], b1 = g_biasp[c + 1];
            #pragma unroll
            for (int h = 0; h < 2; ++h) {
                int r = row0 + mi * 16 + h * 8;
                float2 v;
                v.x = acc[mi][ni][2 * h]     + b0;
                v.y = acc[mi][ni][2 * h + 1] + b1;
                *reinterpret_cast<float2*>(out + (size_t)r * N_DIM + c) = v;
            }
        }
    }
}

// ---------------------------------------------------------------------------
extern "C" void kernel_launch(void* const* d_in, const int* in_sizes, int n_in,
                              void* d_out, int out_size) {
    const float* x          = (const float*)d_in[0];
    const float* W          = (const float*)d_in[1];
    const float* bias       = (const float*)d_in[2];
    const float* B_lora     = (const float*)d_in[3];
    const float* A_lora     = (const float*)d_in[4];
    const float* delta_bias = (const float*)d_in[5];
    float* out = (float*)d_out;

    cudaFuncSetAttribute(gemm_tf32, cudaFuncAttributeMaxDynamicSharedMemorySize, SMEM_BYTES);
    cudaFuncSetAttribute(gemm_tf32, cudaFuncAttributePreferredSharedMemoryCarveout,
                         cudaSharedmemCarveoutMaxShared);

    prep_x<<<(int)(((size_t)M_DIM * K_DIM / 4) / 256), 256>>>(x);
    prep_w<<<dim3(K_DIM / 128, N_DIM / 16), 256>>>(W, B_lora, A_lora);
    prep_bias<<<(N_DIM + 255) / 256, 256>>>(bias, delta_bias);
    gemm_tf32<<<dim3(N_DIM / BN, M_DIM / BM), 256, SMEM_BYTES>>>(out);
}